// round 7
// baseline (speedup 1.0000x reference)
#include <cuda_runtime.h>
#include <cuda_fp16.h>
#include <cstdint>

#define CIN 3
#define NY  31
#define POS 961
#define POq 48

// ---- smem layout (bytes) ----
#define SBIAS 0          // 48 floats
#define AHI0  1024       // A tiles: 128 rows x 64B (32 halves), swizzled
#define ALO0  9216
#define BHI0  17408      // B tiles: 32 rows x 128B (48 halves used), swizzled
#define BLO0  21504
#define AHI1  25600
#define ALO1  33792
#define BHI1  41984
#define BLO1  46080
#define SMEM_BYTES 50176

// A-tile swizzle: row is 64B = 4 chunks of 16B. 2-bit XOR only (kc in 0..3).
#define ASWZ(row, kc) ((uint32_t)(((kc) ^ (((row) >> 1) & 3u) ^ (((row) >> 3) & 3u))))

__device__ __forceinline__ uint32_t smem_u32(const void* p) {
    uint32_t a;
    asm("{ .reg .u64 t; cvta.to.shared.u64 t, %1; cvt.u32.u64 %0, t; }" : "=r"(a) : "l"(p));
    return a;
}
__device__ __forceinline__ void ldsm_x4(uint32_t& r0, uint32_t& r1, uint32_t& r2, uint32_t& r3,
                                        uint32_t a) {
    asm volatile("ldmatrix.sync.aligned.m8n8.x4.shared.b16 {%0,%1,%2,%3}, [%4];"
                 : "=r"(r0), "=r"(r1), "=r"(r2), "=r"(r3) : "r"(a));
}
__device__ __forceinline__ void ldsm_x4t(uint32_t& r0, uint32_t& r1, uint32_t& r2, uint32_t& r3,
                                         uint32_t a) {
    asm volatile("ldmatrix.sync.aligned.m8n8.x4.trans.shared.b16 {%0,%1,%2,%3}, [%4];"
                 : "=r"(r0), "=r"(r1), "=r"(r2), "=r"(r3) : "r"(a));
}
__device__ __forceinline__ void mma16816(float& d0, float& d1, float& d2, float& d3,
                                         uint32_t a0, uint32_t a1, uint32_t a2, uint32_t a3,
                                         uint32_t b0, uint32_t b1) {
    asm volatile("mma.sync.aligned.m16n8k16.row.col.f32.f16.f16.f32 "
                 "{%0,%1,%2,%3}, {%4,%5,%6,%7}, {%8,%9}, {%0,%1,%2,%3};"
                 : "+f"(d0), "+f"(d1), "+f"(d2), "+f"(d3)
                 : "r"(a0), "r"(a1), "r"(a2), "r"(a3), "r"(b0), "r"(b1));
}
__device__ __forceinline__ void split2(float v0, float v1, uint32_t& hi, uint32_t& lo) {
    __half h0 = __float2half_rn(v0), h1 = __float2half_rn(v1);
    __half l0 = __float2half_rn(v0 - __half2float(h0));
    __half l1 = __float2half_rn(v1 - __half2float(h1));
    hi = (uint32_t)__half_as_ushort(h0) | ((uint32_t)__half_as_ushort(h1) << 16);
    lo = (uint32_t)__half_as_ushort(l0) | ((uint32_t)__half_as_ushort(l1) << 16);
}
__device__ __forceinline__ void sts64(uint32_t a, uint32_t v0, uint32_t v1) {
    asm volatile("st.shared.v2.b32 [%0], {%1,%2};" :: "r"(a), "r"(v0), "r"(v1) : "memory");
}
__device__ __forceinline__ void sts16(uint32_t a, unsigned short v) {
    asm volatile("st.shared.u16 [%0], %1;" :: "r"(a), "h"(v) : "memory");
}

extern __shared__ char smem[];

__global__ void __launch_bounds__(256, 2)
ttn_conv_hmma_kernel(const float* __restrict__ x,
                     const float* __restrict__ w,
                     const float* __restrict__ bias,
                     float* __restrict__ out)
{
    const int pos   = blockIdx.x;
    const int xx    = pos / NY;
    const int yy    = pos - xx * NY;
    const int tid   = threadIdx.x;
    const int lane  = tid & 31;
    const int wid   = tid >> 5;
    const int role  = tid >> 7;      // 0: weights/B,  1: x/A
    const int rlane = tid & 127;
    const uint32_t sb = smem_u32(smem);
    float* sbias = (float*)(smem + SBIAS);

    if (tid < POq) {
        int p = tid / 6, o = tid - p * 6;
        sbias[tid] = bias[((p * 31 + xx) * 31 + yy) * 6 + o];
    }

    // role-0 weight load mapping
    const int bp  = rlane >> 4;      // p block (0..7)
    const int t16 = rlane & 15;

    float D[24];
    #pragma unroll
    for (int i = 0; i < 24; i++) D[i] = 0.f;

    // role-0 state: 2-deep LDG prefetch
    float4 fb[2][3];
    // role-1 state: patch precursors + x prefetch
    float ab[16], cd[16], xv[16];

    auto ldg_w = [&](int chunk, int slot) {
        int c = chunk >> 3, s = chunk & 7;
        const float* gw = w + ((size_t)(c * 8 + bp) * POS + pos) * 1536 + s * 192;
        #pragma unroll
        for (int r = 0; r < 3; r++) fb[slot][r] = ((const float4*)gw)[t16 + 16 * r];
    };
    auto load_x = [&](int c) {
        const float* xp = x + ((size_t)rlane * CIN + c) * 4096 + xx * 32 + yy;
        #pragma unroll
        for (int i = 0; i < 4; i++) {
            xv[i]      = xp[i * 1024];
            xv[4 + i]  = xp[i * 1024 + 32];
            xv[8 + i]  = xp[i * 1024 + 1];
            xv[12 + i] = xp[i * 1024 + 33];
        }
    };
    auto conv_x = [&]() {
        #pragma unroll
        for (int t = 0; t < 16; t++) {
            ab[t] = xv[t >> 2] * xv[4 + (t & 3)];
            cd[t] = xv[8 + (t >> 2)] * xv[12 + (t & 3)];
        }
    };
    auto stage = [&](int chunk) {
        const int s   = chunk & 7;
        const int buf = chunk & 1;
        if (role == 1) {
            // A: row = rlane, k-local 0..31 -> ab[2s+h]*cd[j]
            const uint32_t ah = sb + (buf ? AHI1 : AHI0);
            const uint32_t al = sb + (buf ? ALO1 : ALO0);
            const uint32_t row = (uint32_t)rlane;
            #pragma unroll
            for (int h = 0; h < 2; h++) {
                const float abv = ab[s * 2 + h];
                #pragma unroll
                for (int g4 = 0; g4 < 4; g4++) {
                    float v0 = abv * cd[g4 * 4 + 0];
                    float v1 = abv * cd[g4 * 4 + 1];
                    float v2 = abv * cd[g4 * 4 + 2];
                    float v3 = abv * cd[g4 * 4 + 3];
                    uint32_t h01, l01, h23, l23;
                    split2(v0, v1, h01, l01);
                    split2(v2, v3, h23, l23);
                    uint32_t kc  = (uint32_t)(h * 2 + (g4 >> 1));
                    uint32_t off = row * 64u + 16u * ASWZ(row, kc) + (uint32_t)(g4 & 1) * 8u;
                    sts64(ah + off, h01, h23);
                    sts64(al + off, l01, l23);
                }
            }
        } else {
            // B: transpose [k-local][o] -> rows k (128B, swizzled), col n = bp*6+o
            const uint32_t bh = sb + (buf ? BHI1 : BHI0);
            const uint32_t bl = sb + (buf ? BLO1 : BLO0);
            const int slot = chunk & 1;   // chunk parity == fb slot holding it
            #pragma unroll
            for (int r = 0; r < 3; r++) {
                const float* fp = &fb[slot][r].x;
                #pragma unroll
                for (int u = 0; u < 4; u++) {
                    int e = t16 * 4 + u + r * 64;       // 0..191
                    int k = e / 6, o = e - 6 * k;
                    uint32_t n   = (uint32_t)(bp * 6 + o);
                    uint32_t off = (uint32_t)k * 128u + 16u * ((n >> 3) ^ ((uint32_t)k & 7u))
                                 + (n & 7u) * 2u;
                    float v = fp[u];
                    __half hh = __float2half_rn(v);
                    __half hl = __float2half_rn(v - __half2float(hh));
                    sts16(bh + off, __half_as_ushort(hh));
                    sts16(bl + off, __half_as_ushort(hl));
                }
            }
        }
    };
    auto compute = [&](int buf) {
        const uint32_t ah = sb + (buf ? AHI1 : AHI0);
        const uint32_t al = sb + (buf ? ALO1 : ALO0);
        const uint32_t bh = sb + (buf ? BHI1 : BHI0);
        const uint32_t bl = sb + (buf ? BLO1 : BLO0);
        #pragma unroll
        for (int s16 = 0; s16 < 2; s16++) {
            // B frags: x4.trans covers 2 n-tiles per instruction
            uint32_t Bh[12], Bl[12];
            uint32_t krow = (uint32_t)(s16 * 16 + ((lane >> 3) & 1) * 8 + (lane & 7));
            #pragma unroll
            for (int ntp = 0; ntp < 3; ntp++) {
                uint32_t n    = (uint32_t)((ntp * 2 + (lane >> 4)) * 8);
                uint32_t boff = krow * 128u + 16u * ((n >> 3) ^ (krow & 7u));
                ldsm_x4t(Bh[ntp * 4], Bh[ntp * 4 + 1], Bh[ntp * 4 + 2], Bh[ntp * 4 + 3], bh + boff);
                ldsm_x4t(Bl[ntp * 4], Bl[ntp * 4 + 1], Bl[ntp * 4 + 2], Bl[ntp * 4 + 3], bl + boff);
            }
            // A frags: this warp's 16-row tile
            uint32_t row = (uint32_t)(wid * 16 + (lane & 15));
            uint32_t kc  = (uint32_t)(s16 * 2 + (lane >> 4));
            uint32_t aoff = row * 64u + 16u * ASWZ(row, kc);
            uint32_t Ah[4], Al[4];
            ldsm_x4(Ah[0], Ah[1], Ah[2], Ah[3], ah + aoff);
            ldsm_x4(Al[0], Al[1], Al[2], Al[3], al + aoff);
            #pragma unroll
            for (int nt = 0; nt < 6; nt++) {
                float* d = D + nt * 4;
                uint32_t b0 = (nt & 1) ? Bh[(nt >> 1) * 4 + 2] : Bh[(nt >> 1) * 4 + 0];
                uint32_t b1 = (nt & 1) ? Bh[(nt >> 1) * 4 + 3] : Bh[(nt >> 1) * 4 + 1];
                uint32_t c0 = (nt & 1) ? Bl[(nt >> 1) * 4 + 2] : Bl[(nt >> 1) * 4 + 0];
                uint32_t c1 = (nt & 1) ? Bl[(nt >> 1) * 4 + 3] : Bl[(nt >> 1) * 4 + 1];
                mma16816(d[0], d[1], d[2], d[3], Ah[0], Ah[1], Ah[2], Ah[3], b0, b1);
                mma16816(d[0], d[1], d[2], d[3], Ah[0], Ah[1], Ah[2], Ah[3], c0, c1);
                mma16816(d[0], d[1], d[2], d[3], Al[0], Al[1], Al[2], Al[3], b0, b1);
            }
        }
    };

    // ---- prologue ----
    if (role == 0) { ldg_w(0, 0); ldg_w(1, 1); }
    else           { load_x(0); conv_x(); }
    stage(0);
    __syncthreads();

    // ---- pipeline ----
    #pragma unroll 1
    for (int chunk = 0; chunk < 24; chunk++) {
        if (role == 0) {
            if (chunk + 2 < 24) ldg_w(chunk + 2, chunk & 1);
        } else {
            if (chunk == 5 || chunk == 13) load_x((chunk + 3) >> 3);
        }
        compute(chunk & 1);
        if (chunk < 23) {
            if (role == 1 && ((chunk + 1) & 7) == 0) conv_x();
            stage(chunk + 1);
        }
        __syncthreads();
    }

    // ---- epilogue ----
    #pragma unroll
    for (int nt = 0; nt < 6; nt++)
        #pragma unroll
        for (int r = 0; r < 4; r++) {
            int row = wid * 16 + (lane >> 2) + ((r >= 2) ? 8 : 0);
            int q   = nt * 8 + (lane & 3) * 2 + (r & 1);
            out[((size_t)row * POq + q) * POS + pos] = D[nt * 4 + r] + sbias[q];
        }
}

extern "C" void kernel_launch(void* const* d_in, const int* in_sizes, int n_in,
                              void* d_out, int out_size) {
    const float* x    = (const float*)d_in[0];
    const float* w    = (const float*)d_in[1];
    const float* bias = (const float*)d_in[2];
    float* out        = (float*)d_out;
    (void)in_sizes; (void)n_in; (void)out_size;

    cudaFuncSetAttribute(ttn_conv_hmma_kernel,
                         cudaFuncAttributeMaxDynamicSharedMemorySize, SMEM_BYTES);
    ttn_conv_hmma_kernel<<<POS, 256, SMEM_BYTES>>>(x, w, bias, out);
}

// round 8
// speedup vs baseline: 1.1410x; 1.1410x over previous
#include <cuda_runtime.h>
#include <cuda_fp16.h>
#include <cstdint>

#define CIN 3
#define NY  31
#define POS 961
#define POq 48

// ---- smem layout (bytes) ----
#define SBIAS 0          // 48 floats
#define AHI0  1024       // A tile: 128 rows x 64B (32 halves), swizzled (hi plane only)
#define BHI0  9216       // B tiles: 32 rows x 128B (48 halves used), swizzled
#define BLO0  13312
#define AHI1  17408
#define BHI1  25600
#define BLO1  29696
#define SMEM_BYTES 33792

// A-tile swizzle: row is 64B = 4 chunks of 16B. 2-bit XOR only (kc in 0..3).
#define ASWZ(row, kc) ((uint32_t)(((kc) ^ (((row) >> 1) & 3u) ^ (((row) >> 3) & 3u))))

__device__ __forceinline__ uint32_t smem_u32(const void* p) {
    uint32_t a;
    asm("{ .reg .u64 t; cvta.to.shared.u64 t, %1; cvt.u32.u64 %0, t; }" : "=r"(a) : "l"(p));
    return a;
}
__device__ __forceinline__ void ldsm_x4(uint32_t& r0, uint32_t& r1, uint32_t& r2, uint32_t& r3,
                                        uint32_t a) {
    asm volatile("ldmatrix.sync.aligned.m8n8.x4.shared.b16 {%0,%1,%2,%3}, [%4];"
                 : "=r"(r0), "=r"(r1), "=r"(r2), "=r"(r3) : "r"(a));
}
__device__ __forceinline__ void ldsm_x4t(uint32_t& r0, uint32_t& r1, uint32_t& r2, uint32_t& r3,
                                         uint32_t a) {
    asm volatile("ldmatrix.sync.aligned.m8n8.x4.trans.shared.b16 {%0,%1,%2,%3}, [%4];"
                 : "=r"(r0), "=r"(r1), "=r"(r2), "=r"(r3) : "r"(a));
}
__device__ __forceinline__ void mma16816(float& d0, float& d1, float& d2, float& d3,
                                         uint32_t a0, uint32_t a1, uint32_t a2, uint32_t a3,
                                         uint32_t b0, uint32_t b1) {
    asm volatile("mma.sync.aligned.m16n8k16.row.col.f32.f16.f16.f32 "
                 "{%0,%1,%2,%3}, {%4,%5,%6,%7}, {%8,%9}, {%0,%1,%2,%3};"
                 : "+f"(d0), "+f"(d1), "+f"(d2), "+f"(d3)
                 : "r"(a0), "r"(a1), "r"(a2), "r"(a3), "r"(b0), "r"(b1));
}
// pack hi fp16 of two floats
__device__ __forceinline__ uint32_t pack_hi(float v0, float v1) {
    __half h0 = __float2half_rn(v0), h1 = __float2half_rn(v1);
    return (uint32_t)__half_as_ushort(h0) | ((uint32_t)__half_as_ushort(h1) << 16);
}
__device__ __forceinline__ void sts64(uint32_t a, uint32_t v0, uint32_t v1) {
    asm volatile("st.shared.v2.b32 [%0], {%1,%2};" :: "r"(a), "r"(v0), "r"(v1) : "memory");
}
__device__ __forceinline__ void sts32(uint32_t a, uint32_t v) {
    asm volatile("st.shared.b32 [%0], %1;" :: "r"(a), "r"(v) : "memory");
}

extern __shared__ char smem[];

__global__ void __launch_bounds__(128, 3)
ttn_conv_hmma_kernel(const float* __restrict__ x,
                     const float* __restrict__ w,
                     const float* __restrict__ bias,
                     float* __restrict__ out)
{
    const int pos  = blockIdx.x;
    const int xx   = pos / NY;
    const int yy   = pos - xx * NY;
    const int tid  = threadIdx.x;
    const int lane = tid & 31;
    const int wid  = tid >> 5;
    const uint32_t sb = smem_u32(smem);
    float* sbias = (float*)(smem + SBIAS);

    if (tid < POq) {
        int p = tid / 6, o = tid - p * 6;
        sbias[tid] = bias[((p * 31 + xx) * 31 + yy) * 6 + o];
    }

    const int bp  = tid >> 4;     // p block (0..7) for weight loads
    const int t16 = tid & 15;

    float D[48];
    #pragma unroll
    for (int i = 0; i < 48; i++) D[i] = 0.f;

    float ab[16], cd[16], xv[16];
    float4 fb[2][3];              // 2-deep weight prefetch

    auto load_x = [&](int c) {
        const float* xp = x + ((size_t)tid * CIN + c) * 4096 + xx * 32 + yy;
        #pragma unroll
        for (int i = 0; i < 4; i++) {
            xv[i]      = xp[i * 1024];
            xv[4 + i]  = xp[i * 1024 + 32];
            xv[8 + i]  = xp[i * 1024 + 1];
            xv[12 + i] = xp[i * 1024 + 33];
        }
    };
    auto conv_x = [&]() {
        #pragma unroll
        for (int t = 0; t < 16; t++) {
            ab[t] = xv[t >> 2] * xv[4 + (t & 3)];
            cd[t] = xv[8 + (t >> 2)] * xv[12 + (t & 3)];
        }
    };
    auto ldg_w = [&](int chunk) {               // slot = chunk&1
        int c = chunk >> 3, s = chunk & 7;
        const float* gw = w + ((size_t)(c * 8 + bp) * POS + pos) * 1536 + s * 192;
        #pragma unroll
        for (int r = 0; r < 3; r++) fb[chunk & 1][r] = ((const float4*)gw)[t16 + 16 * r];
    };
    auto stage = [&](int chunk) {
        const int s   = chunk & 7;
        const int buf = chunk & 1;
        const uint32_t ah = sb + (buf ? AHI1 : AHI0);
        const uint32_t bh = sb + (buf ? BHI1 : BHI0);
        const uint32_t bl = sb + (buf ? BLO1 : BLO0);

        // A (hi plane only): row = tid, k-local 0..31 -> ab[2s+h]*cd[j]
        const uint32_t row = (uint32_t)tid;
        #pragma unroll
        for (int h = 0; h < 2; h++) {
            const float abv = ab[s * 2 + h];
            #pragma unroll
            for (int g4 = 0; g4 < 4; g4++) {
                float v0 = abv * cd[g4 * 4 + 0];
                float v1 = abv * cd[g4 * 4 + 1];
                float v2 = abv * cd[g4 * 4 + 2];
                float v3 = abv * cd[g4 * 4 + 3];
                uint32_t kc  = (uint32_t)(h * 2 + (g4 >> 1));
                uint32_t off = row * 64u + 16u * ASWZ(row, kc) + (uint32_t)(g4 & 1) * 8u;
                sts64(ah + off, pack_hi(v0, v1), pack_hi(v2, v3));
            }
        }
        // B: hi/lo planes, paired o-values -> one sts32 per plane per pair
        #pragma unroll
        for (int r = 0; r < 3; r++) {
            const float* fp = &fb[chunk & 1][r].x;
            #pragma unroll
            for (int up = 0; up < 2; up++) {
                int e0 = t16 * 4 + up * 2 + r * 64;   // even; e0%6 in {0,2,4} -> same-k pair
                int k  = e0 / 6, o = e0 - 6 * k;
                uint32_t n   = (uint32_t)(bp * 6 + o);         // even
                uint32_t off = (uint32_t)k * 128u + 16u * ((n >> 3) ^ ((uint32_t)k & 7u))
                             + (n & 7u) * 2u;
                float v0 = fp[up * 2], v1 = fp[up * 2 + 1];
                __half h0 = __float2half_rn(v0), h1 = __float2half_rn(v1);
                float l0f = v0 - __half2float(h0), l1f = v1 - __half2float(h1);
                uint32_t hp = (uint32_t)__half_as_ushort(h0)
                            | ((uint32_t)__half_as_ushort(h1) << 16);
                sts32(bh + off, hp);
                sts32(bl + off, pack_hi(l0f, l1f));
            }
        }
    };
    auto compute = [&](int buf) {
        const uint32_t ah = sb + (buf ? AHI1 : AHI0);
        const uint32_t bh = sb + (buf ? BHI1 : BHI0);
        const uint32_t bl = sb + (buf ? BLO1 : BLO0);
        #pragma unroll
        for (int s16 = 0; s16 < 2; s16++) {
            // B frags: x4.trans covers 2 n-tiles per instruction (validated mapping)
            uint32_t Bh[12], Bl[12];
            uint32_t krow = (uint32_t)(s16 * 16 + ((lane >> 3) & 1) * 8 + (lane & 7));
            #pragma unroll
            for (int ntp = 0; ntp < 3; ntp++) {
                uint32_t n    = (uint32_t)((ntp * 2 + (lane >> 4)) * 8);
                uint32_t boff = krow * 128u + 16u * ((n >> 3) ^ (krow & 7u));
                ldsm_x4t(Bh[ntp * 4], Bh[ntp * 4 + 1], Bh[ntp * 4 + 2], Bh[ntp * 4 + 3], bh + boff);
                ldsm_x4t(Bl[ntp * 4], Bl[ntp * 4 + 1], Bl[ntp * 4 + 2], Bl[ntp * 4 + 3], bl + boff);
            }
            #pragma unroll
            for (int mt = 0; mt < 2; mt++) {
                uint32_t row = (uint32_t)(wid * 32 + mt * 16 + (lane & 15));
                uint32_t kc  = (uint32_t)(s16 * 2 + (lane >> 4));
                uint32_t aoff = row * 64u + 16u * ASWZ(row, kc);
                uint32_t Ah[4];
                ldsm_x4(Ah[0], Ah[1], Ah[2], Ah[3], ah + aoff);
                #pragma unroll
                for (int nt = 0; nt < 6; nt++) {
                    float* d = D + (mt * 6 + nt) * 4;
                    uint32_t b0 = (nt & 1) ? Bh[(nt >> 1) * 4 + 2] : Bh[(nt >> 1) * 4 + 0];
                    uint32_t b1 = (nt & 1) ? Bh[(nt >> 1) * 4 + 3] : Bh[(nt >> 1) * 4 + 1];
                    uint32_t c0 = (nt & 1) ? Bl[(nt >> 1) * 4 + 2] : Bl[(nt >> 1) * 4 + 0];
                    uint32_t c1 = (nt & 1) ? Bl[(nt >> 1) * 4 + 3] : Bl[(nt >> 1) * 4 + 1];
                    mma16816(d[0], d[1], d[2], d[3], Ah[0], Ah[1], Ah[2], Ah[3], b0, b1);
                    mma16816(d[0], d[1], d[2], d[3], Ah[0], Ah[1], Ah[2], Ah[3], c0, c1);
                }
            }
        }
    };

    // ---- prologue ----
    load_x(0);
    conv_x();
    ldg_w(0);
    ldg_w(1);
    stage(0);
    __syncthreads();

    // ---- pipeline ----
    #pragma unroll 1
    for (int chunk = 0; chunk < 24; chunk++) {
        if (chunk + 2 < 24) ldg_w(chunk + 2);
        if ((chunk & 7) == 5 && chunk < 21) load_x((chunk >> 3) + 1);
        if (chunk < 23) {
            if (((chunk + 1) & 7) == 0) conv_x();
            stage(chunk + 1);              // STS to other buffer, overlapped by MMAs below
        }
        compute(chunk & 1);
        __syncthreads();
    }

    // ---- epilogue ----
    #pragma unroll
    for (int mt = 0; mt < 2; mt++)
        #pragma unroll
        for (int nt = 0; nt < 6; nt++)
            #pragma unroll
            for (int r = 0; r < 4; r++) {
                int row = wid * 32 + mt * 16 + (lane >> 2) + ((r >= 2) ? 8 : 0);
                int q   = nt * 8 + (lane & 3) * 2 + (r & 1);
                out[((size_t)row * POq + q) * POS + pos] = D[(mt * 6 + nt) * 4 + r] + sbias[q];
            }
}

extern "C" void kernel_launch(void* const* d_in, const int* in_sizes, int n_in,
                              void* d_out, int out_size) {
    const float* x    = (const float*)d_in[0];
    const float* w    = (const float*)d_in[1];
    const float* bias = (const float*)d_in[2];
    float* out        = (float*)d_out;
    (void)in_sizes; (void)n_in; (void)out_size;

    cudaFuncSetAttribute(ttn_conv_hmma_kernel,
                         cudaFuncAttributeMaxDynamicSharedMemorySize, SMEM_BYTES);
    ttn_conv_hmma_kernel<<<POS, 128, SMEM_BYTES>>>(x, w, bias, out);
}

// round 9
// speedup vs baseline: 1.3254x; 1.1616x over previous
#include <cuda_runtime.h>
#include <cuda_fp16.h>
#include <cstdint>

#define CIN 3
#define NY  31
#define POS 961
#define POq 48

// ---- smem layout (bytes) ----
#define SBIAS 0          // 48 floats
#define AHI0  1024       // A tile: 128 rows x 64B (32 halves), swizzled (hi plane only)
#define BHI0  9216       // B tiles: 32 rows x 128B (48 halves used), swizzled
#define BLO0  13312
#define AHI1  17408
#define BHI1  25600
#define BLO1  29696
#define SMEM_BYTES 33792

// A-tile swizzle: row is 64B = 4 chunks of 16B. 2-bit XOR only (kc in 0..3).
#define ASWZ(row, kc) ((uint32_t)(((kc) ^ (((row) >> 1) & 3u) ^ (((row) >> 3) & 3u))))

__device__ __forceinline__ uint32_t smem_u32(const void* p) {
    uint32_t a;
    asm("{ .reg .u64 t; cvta.to.shared.u64 t, %1; cvt.u32.u64 %0, t; }" : "=r"(a) : "l"(p));
    return a;
}
__device__ __forceinline__ void ldsm_x4(uint32_t& r0, uint32_t& r1, uint32_t& r2, uint32_t& r3,
                                        uint32_t a) {
    asm volatile("ldmatrix.sync.aligned.m8n8.x4.shared.b16 {%0,%1,%2,%3}, [%4];"
                 : "=r"(r0), "=r"(r1), "=r"(r2), "=r"(r3) : "r"(a));
}
__device__ __forceinline__ void ldsm_x4t(uint32_t& r0, uint32_t& r1, uint32_t& r2, uint32_t& r3,
                                         uint32_t a) {
    asm volatile("ldmatrix.sync.aligned.m8n8.x4.trans.shared.b16 {%0,%1,%2,%3}, [%4];"
                 : "=r"(r0), "=r"(r1), "=r"(r2), "=r"(r3) : "r"(a));
}
__device__ __forceinline__ void mma16816(float& d0, float& d1, float& d2, float& d3,
                                         uint32_t a0, uint32_t a1, uint32_t a2, uint32_t a3,
                                         uint32_t b0, uint32_t b1) {
    asm volatile("mma.sync.aligned.m16n8k16.row.col.f32.f16.f16.f32 "
                 "{%0,%1,%2,%3}, {%4,%5,%6,%7}, {%8,%9}, {%0,%1,%2,%3};"
                 : "+f"(d0), "+f"(d1), "+f"(d2), "+f"(d3)
                 : "r"(a0), "r"(a1), "r"(a2), "r"(a3), "r"(b0), "r"(b1));
}
__device__ __forceinline__ uint32_t pack_hi(float v0, float v1) {
    __half h0 = __float2half_rn(v0), h1 = __float2half_rn(v1);
    return (uint32_t)__half_as_ushort(h0) | ((uint32_t)__half_as_ushort(h1) << 16);
}
__device__ __forceinline__ void sts64(uint32_t a, uint32_t v0, uint32_t v1) {
    asm volatile("st.shared.v2.b32 [%0], {%1,%2};" :: "r"(a), "r"(v0), "r"(v1) : "memory");
}
__device__ __forceinline__ void sts32(uint32_t a, uint32_t v) {
    asm volatile("st.shared.b32 [%0], %1;" :: "r"(a), "r"(v) : "memory");
}

extern __shared__ char smem[];

__global__ void __launch_bounds__(128, 4)
ttn_conv_hmma_kernel(const float* __restrict__ x,
                     const float* __restrict__ w,
                     const float* __restrict__ bias,
                     float* __restrict__ out)
{
    const int pos  = blockIdx.x;
    const int xx   = pos / NY;
    const int yy   = pos - xx * NY;
    const int tid  = threadIdx.x;
    const int lane = tid & 31;
    const int wid  = tid >> 5;
    const uint32_t sb = smem_u32(smem);
    float* sbias = (float*)(smem + SBIAS);

    if (tid < POq) {
        int p = tid / 6, o = tid - p * 6;
        sbias[tid] = bias[((p * 31 + xx) * 31 + yy) * 6 + o];
    }

    const int bp  = tid >> 4;     // p block (0..7) for weight loads
    const int t16 = tid & 15;

    float D[48];
    #pragma unroll
    for (int i = 0; i < 48; i++) D[i] = 0.f;

    float xv[16];                 // current c precursors (a,b,c,d x 4)
    float xn[16];                 // prefetched next-c precursors
    float4 fb[2][3];              // 2-deep weight prefetch

    auto load_x_to = [&](int c, float* dst) {
        const float* xp = x + ((size_t)tid * CIN + c) * 4096 + xx * 32 + yy;
        #pragma unroll
        for (int i = 0; i < 4; i++) {
            dst[i]      = xp[i * 1024];
            dst[4 + i]  = xp[i * 1024 + 32];
            dst[8 + i]  = xp[i * 1024 + 1];
            dst[12 + i] = xp[i * 1024 + 33];
        }
    };
    auto commit_xn = [&]() {
        #pragma unroll
        for (int i = 0; i < 16; i++) xv[i] = xn[i];
    };
    auto ldg_w = [&](int chunk) {               // slot = chunk&1
        int c = chunk >> 3, s = chunk & 7;
        const float* gw = w + ((size_t)(c * 8 + bp) * POS + pos) * 1536 + s * 192;
        #pragma unroll
        for (int r = 0; r < 3; r++) fb[chunk & 1][r] = ((const float4*)gw)[t16 + 16 * r];
    };
    auto stage = [&](int chunk) {
        const int s   = chunk & 7;
        const int buf = chunk & 1;
        const uint32_t ah = sb + (buf ? AHI1 : AHI0);
        const uint32_t bh = sb + (buf ? BHI1 : BHI0);
        const uint32_t bl = sb + (buf ? BLO1 : BLO0);

        // A (hi plane only): row = tid; values ab[2s+h]*cd[j], recomputed from xv
        const uint32_t row = (uint32_t)tid;
        #pragma unroll
        for (int h = 0; h < 2; h++) {
            const int t2 = s * 2 + h;
            const float abv = xv[t2 >> 2] * xv[4 + (t2 & 3)];
            #pragma unroll
            for (int g4 = 0; g4 < 4; g4++) {
                const float t0 = abv * xv[8 + g4];
                float v0 = t0 * xv[12 + 0];
                float v1 = t0 * xv[12 + 1];
                float v2 = t0 * xv[12 + 2];
                float v3 = t0 * xv[12 + 3];
                uint32_t kc  = (uint32_t)(h * 2 + (g4 >> 1));
                uint32_t off = row * 64u + 16u * ASWZ(row, kc) + (uint32_t)(g4 & 1) * 8u;
                sts64(ah + off, pack_hi(v0, v1), pack_hi(v2, v3));
            }
        }
        // B: hi/lo planes, paired o-values -> one sts32 per plane per pair
        #pragma unroll
        for (int r = 0; r < 3; r++) {
            const float* fp = &fb[chunk & 1][r].x;
            #pragma unroll
            for (int up = 0; up < 2; up++) {
                int e0 = t16 * 4 + up * 2 + r * 64;   // even; e0%6 in {0,2,4} -> same-k pair
                int k  = e0 / 6, o = e0 - 6 * k;
                uint32_t n   = (uint32_t)(bp * 6 + o);         // even
                uint32_t off = (uint32_t)k * 128u + 16u * ((n >> 3) ^ ((uint32_t)k & 7u))
                             + (n & 7u) * 2u;
                float v0 = fp[up * 2], v1 = fp[up * 2 + 1];
                __half h0 = __float2half_rn(v0), h1 = __float2half_rn(v1);
                float l0f = v0 - __half2float(h0), l1f = v1 - __half2float(h1);
                uint32_t hp = (uint32_t)__half_as_ushort(h0)
                            | ((uint32_t)__half_as_ushort(h1) << 16);
                sts32(bh + off, hp);
                sts32(bl + off, pack_hi(l0f, l1f));
            }
        }
    };
    auto compute = [&](int buf) {
        const uint32_t ah = sb + (buf ? AHI1 : AHI0);
        const uint32_t bh = sb + (buf ? BHI1 : BHI0);
        const uint32_t bl = sb + (buf ? BLO1 : BLO0);
        #pragma unroll
        for (int s16 = 0; s16 < 2; s16++) {
            // B frags: x4.trans covers 2 n-tiles per instruction
            uint32_t Bh[12], Bl[12];
            uint32_t krow = (uint32_t)(s16 * 16 + ((lane >> 3) & 1) * 8 + (lane & 7));
            #pragma unroll
            for (int ntp = 0; ntp < 3; ntp++) {
                uint32_t n    = (uint32_t)((ntp * 2 + (lane >> 4)) * 8);
                uint32_t boff = krow * 128u + 16u * ((n >> 3) ^ (krow & 7u));
                ldsm_x4t(Bh[ntp * 4], Bh[ntp * 4 + 1], Bh[ntp * 4 + 2], Bh[ntp * 4 + 3], bh + boff);
                ldsm_x4t(Bl[ntp * 4], Bl[ntp * 4 + 1], Bl[ntp * 4 + 2], Bl[ntp * 4 + 3], bl + boff);
            }
            #pragma unroll
            for (int mt = 0; mt < 2; mt++) {
                uint32_t row = (uint32_t)(wid * 32 + mt * 16 + (lane & 15));
                uint32_t kc  = (uint32_t)(s16 * 2 + (lane >> 4));
                uint32_t aoff = row * 64u + 16u * ASWZ(row, kc);
                uint32_t Ah[4];
                ldsm_x4(Ah[0], Ah[1], Ah[2], Ah[3], ah + aoff);
                #pragma unroll
                for (int nt = 0; nt < 6; nt++) {
                    float* d = D + (mt * 6 + nt) * 4;
                    uint32_t b0 = (nt & 1) ? Bh[(nt >> 1) * 4 + 2] : Bh[(nt >> 1) * 4 + 0];
                    uint32_t b1 = (nt & 1) ? Bh[(nt >> 1) * 4 + 3] : Bh[(nt >> 1) * 4 + 1];
                    uint32_t c0 = (nt & 1) ? Bl[(nt >> 1) * 4 + 2] : Bl[(nt >> 1) * 4 + 0];
                    uint32_t c1 = (nt & 1) ? Bl[(nt >> 1) * 4 + 3] : Bl[(nt >> 1) * 4 + 1];
                    mma16816(d[0], d[1], d[2], d[3], Ah[0], Ah[1], Ah[2], Ah[3], b0, b1);
                    mma16816(d[0], d[1], d[2], d[3], Ah[0], Ah[1], Ah[2], Ah[3], c0, c1);
                }
            }
        }
    };

    // ---- prologue ----
    load_x_to(0, xv);
    ldg_w(0);
    ldg_w(1);
    stage(0);
    __syncthreads();

    // ---- pipeline ----
    #pragma unroll 1
    for (int chunk = 0; chunk < 24; chunk++) {
        if (chunk + 2 < 24) ldg_w(chunk + 2);
        if ((chunk & 7) == 5 && chunk < 21) load_x_to((chunk >> 3) + 1, xn);
        if ((chunk & 7) == 7 && chunk < 23) commit_xn();
        if (chunk < 23) stage(chunk + 1);      // STS to other buffer, overlapped by MMAs
        compute(chunk & 1);
        __syncthreads();
    }

    // ---- epilogue ----
    #pragma unroll
    for (int mt = 0; mt < 2; mt++)
        #pragma unroll
        for (int nt = 0; nt < 6; nt++)
            #pragma unroll
            for (int r = 0; r < 4; r++) {
                int row = wid * 32 + mt * 16 + (lane >> 2) + ((r >= 2) ? 8 : 0);
                int q   = nt * 8 + (lane & 3) * 2 + (r & 1);
                out[((size_t)row * POq + q) * POS + pos] = D[(mt * 6 + nt) * 4 + r] + sbias[q];
            }
}

extern "C" void kernel_launch(void* const* d_in, const int* in_sizes, int n_in,
                              void* d_out, int out_size) {
    const float* x    = (const float*)d_in[0];
    const float* w    = (const float*)d_in[1];
    const float* bias = (const float*)d_in[2];
    float* out        = (float*)d_out;
    (void)in_sizes; (void)n_in; (void)out_size;

    cudaFuncSetAttribute(ttn_conv_hmma_kernel,
                         cudaFuncAttributeMaxDynamicSharedMemorySize, SMEM_BYTES);
    ttn_conv_hmma_kernel<<<POS, 128, SMEM_BYTES>>>(x, w, bias, out);
}

// round 10
// speedup vs baseline: 1.3408x; 1.0116x over previous
#include <cuda_runtime.h>
#include <cuda_fp16.h>
#include <cstdint>

#define CIN 3
#define NY  31
#define POS 961
#define POq 48

// ---- smem layout (bytes) ----
#define SBIAS 0          // 48 floats
#define A0    1024       // A tile: 128 rows x 128B (64 halves = K64), swizzled, fp16 hi only
#define B0    17408      // B tile: 64 rows x 128B (48 halves used), swizzled, fp16 hi only
#define A1    25600
#define B1    41984
#define SMEM_BYTES 50176

// A swizzle: row = 128B = 8 chunks of 16B, kc in 0..7.
// LDSM (8 rows, fixed kc): (row&7) varies -> distinct. STS (32 rows, fixed kc):
// (row&7) x (row>>3)&7 spreads all 32 lanes -> conflict-free.
#define ASWZ8(row, kc) ((uint32_t)(((kc) ^ ((row) & 7u) ^ (((row) >> 3) & 7u))))

__device__ __forceinline__ uint32_t smem_u32(const void* p) {
    uint32_t a;
    asm("{ .reg .u64 t; cvta.to.shared.u64 t, %1; cvt.u32.u64 %0, t; }" : "=r"(a) : "l"(p));
    return a;
}
__device__ __forceinline__ void ldsm_x4(uint32_t& r0, uint32_t& r1, uint32_t& r2, uint32_t& r3,
                                        uint32_t a) {
    asm volatile("ldmatrix.sync.aligned.m8n8.x4.shared.b16 {%0,%1,%2,%3}, [%4];"
                 : "=r"(r0), "=r"(r1), "=r"(r2), "=r"(r3) : "r"(a));
}
__device__ __forceinline__ void ldsm_x4t(uint32_t& r0, uint32_t& r1, uint32_t& r2, uint32_t& r3,
                                         uint32_t a) {
    asm volatile("ldmatrix.sync.aligned.m8n8.x4.trans.shared.b16 {%0,%1,%2,%3}, [%4];"
                 : "=r"(r0), "=r"(r1), "=r"(r2), "=r"(r3) : "r"(a));
}
__device__ __forceinline__ void mma16816(float& d0, float& d1, float& d2, float& d3,
                                         uint32_t a0, uint32_t a1, uint32_t a2, uint32_t a3,
                                         uint32_t b0, uint32_t b1) {
    asm volatile("mma.sync.aligned.m16n8k16.row.col.f32.f16.f16.f32 "
                 "{%0,%1,%2,%3}, {%4,%5,%6,%7}, {%8,%9}, {%0,%1,%2,%3};"
                 : "+f"(d0), "+f"(d1), "+f"(d2), "+f"(d3)
                 : "r"(a0), "r"(a1), "r"(a2), "r"(a3), "r"(b0), "r"(b1));
}
__device__ __forceinline__ uint32_t pack_hi(float v0, float v1) {
    __half h0 = __float2half_rn(v0), h1 = __float2half_rn(v1);
    return (uint32_t)__half_as_ushort(h0) | ((uint32_t)__half_as_ushort(h1) << 16);
}
__device__ __forceinline__ void sts64(uint32_t a, uint32_t v0, uint32_t v1) {
    asm volatile("st.shared.v2.b32 [%0], {%1,%2};" :: "r"(a), "r"(v0), "r"(v1) : "memory");
}
__device__ __forceinline__ void sts32(uint32_t a, uint32_t v) {
    asm volatile("st.shared.b32 [%0], %1;" :: "r"(a), "r"(v) : "memory");
}

extern __shared__ char smem[];

__global__ void __launch_bounds__(128, 4)
ttn_conv_hmma_kernel(const float* __restrict__ x,
                     const float* __restrict__ w,
                     const float* __restrict__ bias,
                     float* __restrict__ out)
{
    const int pos  = blockIdx.x;
    const int xx   = pos / NY;
    const int yy   = pos - xx * NY;
    const int tid  = threadIdx.x;
    const int lane = tid & 31;
    const int wid  = tid >> 5;
    const uint32_t sb = smem_u32(smem);
    float* sbias = (float*)(smem + SBIAS);

    if (tid < POq) {
        int p = tid / 6, o = tid - p * 6;
        sbias[tid] = bias[((p * 31 + xx) * 31 + yy) * 6 + o];
    }

    const int bp  = tid >> 4;     // p block (0..7) for weight loads
    const int t16 = tid & 15;

    float D[48];
    #pragma unroll
    for (int i = 0; i < 48; i++) D[i] = 0.f;

    float xv[16];                 // current c precursors (a,b,c,d x 4)
    float xn[16];                 // prefetched next-c precursors
    float4 fb[6];                 // weight prefetch for next stage (384 floats / 16 thr / p)

    auto load_x_to = [&](int c, float* dst) {
        const float* xp = x + ((size_t)tid * CIN + c) * 4096 + xx * 32 + yy;
        #pragma unroll
        for (int i = 0; i < 4; i++) {
            dst[i]      = xp[i * 1024];
            dst[4 + i]  = xp[i * 1024 + 32];
            dst[8 + i]  = xp[i * 1024 + 1];
            dst[12 + i] = xp[i * 1024 + 33];
        }
    };
    auto commit_xn = [&]() {
        #pragma unroll
        for (int i = 0; i < 16; i++) xv[i] = xn[i];
    };
    auto ldg_w = [&](int st) {      // stage st covers 384 floats per p-block
        int c = st >> 2;
        const float* gw = w + ((size_t)(c * 8 + bp) * POS + pos) * 1536 + (st & 3) * 384;
        #pragma unroll
        for (int r = 0; r < 6; r++) fb[r] = ((const float4*)gw)[t16 + 16 * r];
    };
    auto stage = [&](int st) {
        const int sl  = st & 3;       // stage-local within c
        const int buf = st & 1;
        const uint32_t ah = sb + (buf ? A1 : A0);
        const uint32_t bh = sb + (buf ? B1 : B0);

        // A: row = tid, k-local 0..63 = ab[sl*4+h] * cd[kl], fp16 hi
        const uint32_t row = (uint32_t)tid;
        #pragma unroll
        for (int h = 0; h < 4; h++) {
            const int t2 = sl * 4 + h;
            const float abv = xv[t2 >> 2] * xv[4 + (t2 & 3)];
            #pragma unroll
            for (int g4 = 0; g4 < 4; g4++) {
                const float t0 = abv * xv[8 + g4];
                float v0 = t0 * xv[12 + 0];
                float v1 = t0 * xv[12 + 1];
                float v2 = t0 * xv[12 + 2];
                float v3 = t0 * xv[12 + 3];
                uint32_t kc  = (uint32_t)(h * 2 + (g4 >> 1));
                uint32_t off = row * 128u + 16u * ASWZ8(row, kc) + (uint32_t)(g4 & 1) * 8u;
                sts64(ah + off, pack_hi(v0, v1), pack_hi(v2, v3));
            }
        }
        // B: fp16 hi plane, paired o-values -> sts32
        #pragma unroll
        for (int r = 0; r < 6; r++) {
            const float* fp = &fb[r].x;
            #pragma unroll
            for (int up = 0; up < 2; up++) {
                int e0 = t16 * 4 + up * 2 + r * 64;   // even; e0%6 in {0,2,4} -> same-k pair
                int k  = e0 / 6, o = e0 - 6 * k;      // k 0..63
                uint32_t n   = (uint32_t)(bp * 6 + o);
                uint32_t off = (uint32_t)k * 128u + 16u * ((n >> 3) ^ ((uint32_t)k & 7u))
                             + (n & 7u) * 2u;
                sts32(bh + off, pack_hi(fp[up * 2], fp[up * 2 + 1]));
            }
        }
    };
    auto compute = [&](int buf) {
        const uint32_t ah = sb + (buf ? A1 : A0);
        const uint32_t bh = sb + (buf ? B1 : B0);
        #pragma unroll
        for (int s16 = 0; s16 < 4; s16++) {
            // B frags: 3 x4.trans cover 6 n-tiles (single plane)
            uint32_t Bh[12];
            uint32_t krow = (uint32_t)(s16 * 16 + ((lane >> 3) & 1) * 8 + (lane & 7));
            #pragma unroll
            for (int ntp = 0; ntp < 3; ntp++) {
                uint32_t n    = (uint32_t)((ntp * 2 + (lane >> 4)) * 8);
                uint32_t boff = krow * 128u + 16u * ((n >> 3) ^ (krow & 7u));
                ldsm_x4t(Bh[ntp * 4], Bh[ntp * 4 + 1], Bh[ntp * 4 + 2], Bh[ntp * 4 + 3], bh + boff);
            }
            #pragma unroll
            for (int mt = 0; mt < 2; mt++) {
                uint32_t row = (uint32_t)(wid * 32 + mt * 16 + (lane & 15));
                uint32_t kc  = (uint32_t)(s16 * 2 + (lane >> 4));
                uint32_t aoff = row * 128u + 16u * ASWZ8(row, kc);
                uint32_t Ah[4];
                ldsm_x4(Ah[0], Ah[1], Ah[2], Ah[3], ah + aoff);
                #pragma unroll
                for (int nt = 0; nt < 6; nt++) {
                    float* d = D + (mt * 6 + nt) * 4;
                    uint32_t b0 = (nt & 1) ? Bh[(nt >> 1) * 4 + 2] : Bh[(nt >> 1) * 4 + 0];
                    uint32_t b1 = (nt & 1) ? Bh[(nt >> 1) * 4 + 3] : Bh[(nt >> 1) * 4 + 1];
                    mma16816(d[0], d[1], d[2], d[3], Ah[0], Ah[1], Ah[2], Ah[3], b0, b1);
                }
            }
        }
    };

    // ---- prologue ----
    load_x_to(0, xv);
    ldg_w(0);
    stage(0);
    __syncthreads();

    // ---- pipeline: 12 stages of K=64 ----
    #pragma unroll 1
    for (int st = 0; st < 12; st++) {
        if (st + 1 < 12) ldg_w(st + 1);              // into fb (consumed by stage(st+1))
        if (st == 2) load_x_to(1, xn);
        if (st == 6) load_x_to(2, xn);
        compute(st & 1);
        if (st == 3 || st == 7) commit_xn();
        if (st < 11) stage(st + 1);                  // STS to other buffer
        __syncthreads();
    }

    // ---- epilogue ----
    #pragma unroll
    for (int mt = 0; mt < 2; mt++)
        #pragma unroll
        for (int nt = 0; nt < 6; nt++)
            #pragma unroll
            for (int r = 0; r < 4; r++) {
                int row = wid * 32 + mt * 16 + (lane >> 2) + ((r >= 2) ? 8 : 0);
                int q   = nt * 8 + (lane & 3) * 2 + (r & 1);
                out[((size_t)row * POq + q) * POS + pos] = D[(mt * 6 + nt) * 4 + r] + sbias[q];
            }
}

extern "C" void kernel_launch(void* const* d_in, const int* in_sizes, int n_in,
                              void* d_out, int out_size) {
    const float* x    = (const float*)d_in[0];
    const float* w    = (const float*)d_in[1];
    const float* bias = (const float*)d_in[2];
    float* out        = (float*)d_out;
    (void)in_sizes; (void)n_in; (void)out_size;

    cudaFuncSetAttribute(ttn_conv_hmma_kernel,
                         cudaFuncAttributeMaxDynamicSharedMemorySize, SMEM_BYTES);
    ttn_conv_hmma_kernel<<<POS, 128, SMEM_BYTES>>>(x, w, bias, out);
}